// round 3
// baseline (speedup 1.0000x reference)
#include <cuda_runtime.h>

#define S_GRID 14
#define N_EL   30
#define NBOX   16
#define NCELLS 196
#define IMG_FLOATS 5880          // 196*30
#define IMG_VEC4   1470          // 5880/4
#define NTHREADS   256
#define VPT        6             // ceil(1470/256) float4s per thread

__device__ double       g_acc;
__device__ unsigned int g_count;

__device__ __forceinline__ float jac(float ax1, float ay1, float ax2, float ay2,
                                     float4 t)
{
    float ltx = fmaxf(ax1, t.x);
    float lty = fmaxf(ay1, t.y);
    float rbx = fminf(ax2, t.z);
    float rby = fminf(ay2, t.w);
    float wi = fmaxf(rbx - ltx, 0.0f);
    float hi = fmaxf(rby - lty, 0.0f);
    float inter = wi * hi;
    float area_a = (ax2 - ax1) * (ay2 - ay1);
    float area_b = (t.z - t.x) * (t.w - t.y);
    float uni = area_a + area_b - inter;
    if (uni == 0.0f) uni = 1.0f;
    return inter / uni;
}

__global__ __launch_bounds__(NTHREADS)
void yolo_kernel(const float* __restrict__ pred,
                 const float* __restrict__ boxes,
                 const int*   __restrict__ classes,
                 float* __restrict__ out,
                 int nblocks)
{
    __shared__ float4 sbox[NCELLS];
    __shared__ int    scls[NCELLS];
    __shared__ double bsum;

    const int tid  = threadIdx.x;
    const int lane = tid & 31;
    const int img  = blockIdx.x;

    if (tid == 0) bsum = 0.0;

    // ---------- encode (warp 0 only): parallel, match_any last-write-wins ----------
    if (tid < 32) {
        #pragma unroll
        for (int k = 0; k < 7; k++) {
            int c = lane + 32 * k;
            if (c < NCELLS) scls[c] = -1;
        }
        int   ci = -1 - lane;          // unique dummies so lanes 16..31 never collide
        float dx = 0.f, dy = 0.f, bw = 0.f, bh = 0.f;
        int   cls = 0;
        if (lane < NBOX) {
            float4 bb = reinterpret_cast<const float4*>(boxes)[img * NBOX + lane];
            cls = classes[img * NBOX + lane];
            bw = bb.z - bb.x;
            bh = bb.w - bb.y;
            float cx = (bb.x + bb.z) * 0.5f;
            float cy = (bb.y + bb.w) * 0.5f;
            const float cell = 1.0f / 14.0f;
            float vx = cx / cell;
            float vy = cy / cell;
            float ix = fminf(fmaxf(ceilf(vx) - 1.0f, 0.0f), 13.0f);
            float iy = fminf(fmaxf(ceilf(vy) - 1.0f, 0.0f), 13.0f);
            dx = vx - ix;
            dy = vy - iy;
            ci = (int)iy * S_GRID + (int)ix;
        }
        __syncwarp();
        unsigned m = __match_any_sync(0xFFFFFFFFu, ci);
        if (lane < NBOX && (31 - __clz(m)) == lane) {   // highest box index = last write
            sbox[ci] = make_float4(dx, dy, bw, bh);
            scls[ci] = cls;
        }
    }

    // ---------- coalesced full-image stream: issue loads before the barrier ----------
    const float* pimg = pred + (size_t)img * IMG_FLOATS;
    const float4* p4 = reinterpret_cast<const float4*>(pimg);
    float4 v[VPT];
    #pragma unroll
    for (int it = 0; it < VPT; it++) {
        int j = tid + NTHREADS * it;
        if (j < IMG_VEC4) v[it] = p4[j];
    }

    __syncthreads();

    float facc = 0.0f;

    // ---------- coord rows (<=16 per image): re-read row, hits L2/L1 ----------
    if (tid < NCELLS) {
        int cl = scls[tid];
        if (cl >= 0) {
            const float2* r2 = reinterpret_cast<const float2*>(pimg + tid * N_EL);
            float2 a0 = r2[0], a1 = r2[1], a2 = r2[2], a3 = r2[3], a4 = r2[4];
            float4 tb = sbox[tid];   // (dx, dy, w, h) target

            // pred box0 = p[0..3] conf p[4]=a2.x ; box1 = p[5..8] conf p[9]=a4.y
            float iou0 = jac(a0.x, a0.y, a1.x, a1.y, tb);
            float iou1 = jac(a2.y, a3.x, a3.y, a4.x, tb);
            bool sel1 = iou1 > iou0;                    // tie -> box0 (argmax first-max)
            float bx  = sel1 ? a2.y : a0.x;
            float by  = sel1 ? a3.x : a0.y;
            float bw_ = sel1 ? a3.y : a1.x;
            float bh_ = sel1 ? a4.x : a1.y;
            float bc  = sel1 ? a4.y : a2.x;

            // class loss over channels 10..29; one-hot at 9+cls => hot at cls-1
            float closs = 0.0f;
            #pragma unroll
            for (int i = 0; i < 10; i++) {
                float2 cc = r2[5 + i];
                float tx_ = (cl == 2 * i + 1) ? 1.0f : 0.0f;
                float ty_ = (cl == 2 * i + 2) ? 1.0f : 0.0f;
                float ex = cc.x - tx_;
                float ey = cc.y - ty_;
                closs += ex * ex + ey * ey;
            }

            float dconf = bc - 1.0f;
            float d0 = bx - tb.x;
            float d1 = by - tb.y;
            float d2 = sqrtf(bw_) - sqrtf(tb.z);
            float d3 = sqrtf(bh_) - sqrtf(tb.w);
            facc += closs + dconf * dconf
                  + 5.0f * (d0 * d0 + d1 * d1 + d2 * d2 + d3 * d3);
        }
    }

    // ---------- streamed noobj conf terms ----------
    // A float4 covers in-row offsets k..k+3 (k = 4j mod 30). It can contain at
    // most ONE conf channel (4 or 9): window length 4 < distance 5, and the
    // mod-30 wrap (k>=27 -> 0..2) never reaches 4 or 9.
    #pragma unroll
    for (int it = 0; it < VPT; it++) {
        int j = tid + NTHREADS * it;
        if (j < IMG_VEC4) {
            int idx = 4 * j;
            int r = idx / N_EL;            // magic-multiply
            int k = idx - N_EL * r;
            int d4 = 4 - k;
            int d9 = 9 - k;
            bool h4 = (unsigned)d4 < 4u;
            bool h9 = (unsigned)d9 < 4u;
            if (h4 || h9) {
                int i = h4 ? d4 : d9;
                float4 vv = v[it];
                float val = (i == 0) ? vv.x : (i == 1) ? vv.y : (i == 2) ? vv.z : vv.w;
                if (scls[r] < 0) facc += 0.5f * val * val;
            }
        }
    }

    // ---------- reduce ----------
    #pragma unroll
    for (int o = 16; o; o >>= 1)
        facc += __shfl_xor_sync(0xFFFFFFFFu, facc, o);
    if (lane == 0) atomicAdd(&bsum, (double)facc);
    __syncthreads();

    if (tid == 0) {
        atomicAdd(&g_acc, bsum);
        __threadfence();
        unsigned done = atomicAdd(&g_count, 1u);
        if (done == (unsigned)(nblocks - 1)) {
            double total = atomicAdd(&g_acc, 0.0);   // coherent read of final sum
            out[0] = (float)total;
            g_acc = 0.0;          // reset for next graph replay
            g_count = 0u;
        }
    }
}

extern "C" void kernel_launch(void* const* d_in, const int* in_sizes, int n_in,
                              void* d_out, int out_size)
{
    const float* pred    = (const float*)d_in[0];   // [batch, 5880]
    const float* boxes   = (const float*)d_in[1];   // [batch, 16, 4]
    const int*   classes = (const int*)d_in[2];     // [batch, 16]
    float* out = (float*)d_out;

    int batch = in_sizes[0] / IMG_FLOATS;           // 4096 blocks, one per image

    yolo_kernel<<<batch, NTHREADS>>>(pred, boxes, classes, out, batch);
}

// round 4
// speedup vs baseline: 1.6827x; 1.6827x over previous
#include <cuda_runtime.h>

#define S_GRID 14
#define N_EL   30
#define NBOX   16
#define NCELLS 196
#define IMG_FLOATS 5880          // 196*30
#define IMG_VEC4   1470
#define NTHREADS   256
#define NBLOCKS    1184          // 148 SMs * 8 blocks

__device__ double       g_acc;
__device__ unsigned int g_count;

__device__ __forceinline__ float jac(float ax1, float ay1, float ax2, float ay2,
                                     float tx, float ty, float tz, float tw)
{
    float ltx = fmaxf(ax1, tx);
    float lty = fmaxf(ay1, ty);
    float rbx = fminf(ax2, tz);
    float rby = fminf(ay2, tw);
    float wi = fmaxf(rbx - ltx, 0.0f);
    float hi = fmaxf(rby - lty, 0.0f);
    float inter = wi * hi;
    float area_a = (ax2 - ax1) * (ay2 - ay1);
    float area_b = (tz - tx) * (tw - ty);
    float uni = area_a + area_b - inter;
    if (uni == 0.0f) uni = 1.0f;
    return inter / uni;
}

// conf extract: idx = 4*j, k = idx mod 30 (k is even).
// float4 covers in-row offsets k..k+3: contains ch4 iff k in {2,4}, ch9 iff k in {6,8}.
__device__ __forceinline__ float conf_of(float4 v, unsigned k)
{
    float c = 0.0f;
    if (k == 2u)      c = v.z;
    else if (k == 4u) c = v.x;
    else if (k == 6u) c = v.w;
    else if (k == 8u) c = v.y;
    return c;
}

__global__ __launch_bounds__(NTHREADS)
void yolo_kernel(const float* __restrict__ pred,
                 const float* __restrict__ boxes,
                 const int*   __restrict__ classes,
                 float* __restrict__ out,
                 int batch)
{
    __shared__ double bsum;

    const int tid  = threadIdx.x;
    const int lane = tid & 31;
    const int gwarp = (blockIdx.x * NTHREADS + tid) >> 5;

    if (tid == 0) bsum = 0.0;

    float facc = 0.0f;

    // ================= coord-correction phase (one warp per image) =================
    // total warps (NBLOCKS*8 = 9472) >= batch, so the loop runs at most once per warp.
    for (int img = gwarp; img < batch; img += NBLOCKS * (NTHREADS / 32)) {
        int   ci = -1 - lane;              // unique dummies for lanes 16..31
        float dx = 0.f, dy = 0.f, bw = 0.f, bh = 0.f;
        int   cls = 0;
        if (lane < NBOX) {
            float4 bb = reinterpret_cast<const float4*>(boxes)[img * NBOX + lane];
            cls = classes[img * NBOX + lane];
            bw = bb.z - bb.x;
            bh = bb.w - bb.y;
            float cx = (bb.x + bb.z) * 0.5f;
            float cy = (bb.y + bb.w) * 0.5f;
            float vx = cx * 14.0f;
            float vy = cy * 14.0f;
            float ix = fminf(fmaxf(ceilf(vx) - 1.0f, 0.0f), 13.0f);
            float iy = fminf(fmaxf(ceilf(vy) - 1.0f, 0.0f), 13.0f);
            dx = vx - ix;
            dy = vy - iy;
            ci = (int)iy * S_GRID + (int)ix;
        }
        unsigned m = __match_any_sync(0xFFFFFFFFu, ci);
        // winner = highest lane in its same-cell group = LAST writer in JAX scatter
        // order; its own (dx,dy,bw,bh,cls) are exactly the cell's target values.
        if (lane < NBOX && (31 - __clz(m)) == lane) {
            const float2* r2 = reinterpret_cast<const float2*>(pred)
                             + (size_t)img * (IMG_FLOATS / 2) + ci * (N_EL / 2);
            float2 a0 = r2[0], a1 = r2[1], a2 = r2[2], a3 = r2[3], a4 = r2[4];
            // pred box0 = p[0..3], conf p[4]=a2.x ; box1 = p[5..8], conf p[9]=a4.y
            float iou0 = jac(a0.x, a0.y, a1.x, a1.y, dx, dy, bw, bh);
            float iou1 = jac(a2.y, a3.x, a3.y, a4.x, dx, dy, bw, bh);
            bool sel1 = iou1 > iou0;       // tie -> box0 (argmax first-max)
            float bx  = sel1 ? a2.y : a0.x;
            float by  = sel1 ? a3.x : a0.y;
            float bw_ = sel1 ? a3.y : a1.x;
            float bh_ = sel1 ? a4.x : a1.y;
            float bc  = sel1 ? a4.y : a2.x;

            // class loss over channels 10..29; one-hot at 9+cls => hot at cls-1
            float closs = 0.0f;
            #pragma unroll
            for (int i = 0; i < 10; i++) {
                float2 cc = r2[5 + i];
                float ex = cc.x - ((cls == 2 * i + 1) ? 1.0f : 0.0f);
                float ey = cc.y - ((cls == 2 * i + 2) ? 1.0f : 0.0f);
                closs += ex * ex + ey * ey;
            }

            float dconf = bc - 1.0f;
            float d0 = bx - dx;
            float d1 = by - dy;
            float d2 = sqrtf(bw_) - sqrtf(bw);
            float d3 = sqrtf(bh_) - sqrtf(bh);
            // subtract this row's conf-squared terms (the stream phase adds them
            // for ALL rows unconditionally)
            facc += closs + dconf * dconf
                  + 5.0f * (d0 * d0 + d1 * d1 + d2 * d2 + d3 * d3)
                  - 0.5f * (a2.x * a2.x + a4.y * a4.y);
        }
    }

    // ================= streaming phase: sum 0.5*(p4^2 + p9^2) over ALL rows =======
    {
        const float4* P = reinterpret_cast<const float4*>(pred);
        const int total4 = batch * IMG_VEC4;
        const int stride = NBLOCKS * NTHREADS;
        int j = blockIdx.x * NTHREADS + tid;

        while (j + 3 * stride < total4) {
            float4 v0 = P[j];
            float4 v1 = P[j + stride];
            float4 v2 = P[j + 2 * stride];
            float4 v3 = P[j + 3 * stride];
            unsigned k0 = (unsigned)(4 * j) % 30u;
            unsigned k1 = (unsigned)(4 * (j + stride)) % 30u;
            unsigned k2 = (unsigned)(4 * (j + 2 * stride)) % 30u;
            unsigned k3 = (unsigned)(4 * (j + 3 * stride)) % 30u;
            float c0 = conf_of(v0, k0);
            float c1 = conf_of(v1, k1);
            float c2 = conf_of(v2, k2);
            float c3 = conf_of(v3, k3);
            facc = fmaf(0.5f * c0, c0, facc);
            facc = fmaf(0.5f * c1, c1, facc);
            facc = fmaf(0.5f * c2, c2, facc);
            facc = fmaf(0.5f * c3, c3, facc);
            j += 4 * stride;
        }
        while (j < total4) {
            float4 v = P[j];
            unsigned k = (unsigned)(4 * j) % 30u;
            float c = conf_of(v, k);
            facc = fmaf(0.5f * c, c, facc);
            j += stride;
        }
    }

    // ================= reduce ================================================
    #pragma unroll
    for (int o = 16; o; o >>= 1)
        facc += __shfl_xor_sync(0xFFFFFFFFu, facc, o);
    if (lane == 0) atomicAdd(&bsum, (double)facc);
    __syncthreads();

    if (tid == 0) {
        atomicAdd(&g_acc, bsum);
        __threadfence();
        unsigned done = atomicAdd(&g_count, 1u);
        if (done == (unsigned)(NBLOCKS - 1)) {
            double total = atomicAdd(&g_acc, 0.0);   // coherent read of final sum
            out[0] = (float)total;
            g_acc = 0.0;          // reset for next graph replay
            g_count = 0u;
        }
    }
}

extern "C" void kernel_launch(void* const* d_in, const int* in_sizes, int n_in,
                              void* d_out, int out_size)
{
    const float* pred    = (const float*)d_in[0];   // [batch, 5880]
    const float* boxes   = (const float*)d_in[1];   // [batch, 16, 4]
    const int*   classes = (const int*)d_in[2];     // [batch, 16]
    float* out = (float*)d_out;

    int batch = in_sizes[0] / IMG_FLOATS;

    yolo_kernel<<<NBLOCKS, NTHREADS>>>(pred, boxes, classes, out, batch);
}

// round 5
// speedup vs baseline: 2.6630x; 1.5826x over previous
#include <cuda_runtime.h>

#define S_GRID 14
#define N_EL   30
#define NBOX   16
#define IMG_FLOATS 5880              // 196*30
#define CONF_PER_IMG 392             // 196 rows * 2 conf channels
#define NTHREADS   256
#define NBLOCKS    1216              // 152 SMs * 8 blocks (full wave)

__device__ double       g_acc;
__device__ unsigned int g_count;

__device__ __forceinline__ float jac(float ax1, float ay1, float ax2, float ay2,
                                     float tx, float ty, float tz, float tw)
{
    float ltx = fmaxf(ax1, tx);
    float lty = fmaxf(ay1, ty);
    float rbx = fminf(ax2, tz);
    float rby = fminf(ay2, tw);
    float wi = fmaxf(rbx - ltx, 0.0f);
    float hi = fmaxf(rby - lty, 0.0f);
    float inter = wi * hi;
    float area_a = (ax2 - ax1) * (ay2 - ay1);
    float area_b = (tz - tx) * (tw - ty);
    float uni = area_a + area_b - inter;
    if (uni == 0.0f) uni = 1.0f;
    return inter / uni;
}

__global__ __launch_bounds__(NTHREADS)
void yolo_kernel(const float* __restrict__ pred,
                 const float* __restrict__ boxes,
                 const int*   __restrict__ classes,
                 float* __restrict__ out,
                 int batch)
{
    __shared__ double bsum;

    const int tid   = threadIdx.x;
    const int lane  = tid & 31;
    const int gwarp = (blockIdx.x * NTHREADS + tid) >> 5;

    if (tid == 0) bsum = 0.0;

    float facc = 0.0f;

    // ============ coord-correction phase (one warp per image) =================
    for (int img = gwarp; img < batch; img += NBLOCKS * (NTHREADS / 32)) {
        int   ci = -1 - lane;              // unique dummies for lanes 16..31
        float dx = 0.f, dy = 0.f, bw = 0.f, bh = 0.f;
        int   cls = 0;
        if (lane < NBOX) {
            float4 bb = reinterpret_cast<const float4*>(boxes)[img * NBOX + lane];
            cls = classes[img * NBOX + lane];
            bw = bb.z - bb.x;
            bh = bb.w - bb.y;
            float cx = (bb.x + bb.z) * 0.5f;
            float cy = (bb.y + bb.w) * 0.5f;
            float vx = cx * 14.0f;
            float vy = cy * 14.0f;
            float ix = fminf(fmaxf(ceilf(vx) - 1.0f, 0.0f), 13.0f);
            float iy = fminf(fmaxf(ceilf(vy) - 1.0f, 0.0f), 13.0f);
            dx = vx - ix;
            dy = vy - iy;
            ci = (int)iy * S_GRID + (int)ix;
        }
        unsigned m = __match_any_sync(0xFFFFFFFFu, ci);
        // winner = highest lane in same-cell group = LAST writer (JAX scatter order);
        // its own (dx,dy,bw,bh,cls) ARE the cell's target values.
        if (lane < NBOX && (31 - __clz(m)) == lane) {
            const float2* r2 = reinterpret_cast<const float2*>(pred)
                             + (size_t)img * (IMG_FLOATS / 2) + ci * (N_EL / 2);
            float2 a0 = r2[0], a1 = r2[1], a2 = r2[2], a3 = r2[3], a4 = r2[4];
            // pred box0 = p[0..3], conf p[4]=a2.x ; box1 = p[5..8], conf p[9]=a4.y
            float iou0 = jac(a0.x, a0.y, a1.x, a1.y, dx, dy, bw, bh);
            float iou1 = jac(a2.y, a3.x, a3.y, a4.x, dx, dy, bw, bh);
            bool sel1 = iou1 > iou0;       // tie -> box0 (argmax first-max)
            float bx  = sel1 ? a2.y : a0.x;
            float by  = sel1 ? a3.x : a0.y;
            float bw_ = sel1 ? a3.y : a1.x;
            float bh_ = sel1 ? a4.x : a1.y;
            float bc  = sel1 ? a4.y : a2.x;

            // class loss over channels 10..29; one-hot at 9+cls => hot at cls-1
            float closs = 0.0f;
            #pragma unroll
            for (int i = 0; i < 10; i++) {
                float2 cc = r2[5 + i];
                float ex = cc.x - ((cls == 2 * i + 1) ? 1.0f : 0.0f);
                float ey = cc.y - ((cls == 2 * i + 2) ? 1.0f : 0.0f);
                closs += ex * ex + ey * ey;
            }

            float dconf = bc - 1.0f;
            float d0 = bx - dx;
            float d1 = by - dy;
            float d2 = sqrtf(bw_) - sqrtf(bw);
            float d3 = sqrtf(bh_) - sqrtf(bh);
            // subtract this row's conf terms (stream phase adds them for ALL rows)
            facc += closs + dconf * dconf
                  + 5.0f * (d0 * d0 + d1 * d1 + d2 * d2 + d3 * d3)
                  - 0.5f * (a2.x * a2.x + a4.y * a4.y);
        }
    }

    // ============ streaming phase: ONLY the conf scalars ======================
    // Conf channels (==4,9 mod 30) repeat per 60-float period at offsets
    // {4, 9, 34, 39}. q = conf id; fidx = 60*(q>>2) + FOFF[q&3].
    // Grid stride T % 4 == 0 keeps q&3 fixed per thread -> constant increment.
    {
        const int total_q = batch * CONF_PER_IMG;
        const int T = NBLOCKS * NTHREADS;          // % 4 == 0
        int q = blockIdx.x * NTHREADS + tid;

        int r = q & 3;
        int foff = (r == 0) ? 4 : (r == 1) ? 9 : (r == 2) ? 34 : 39;
        int fidx = 60 * (q >> 2) + foff;
        const int finc = 15 * T;                   // fidx step per q-step of T

        float s0 = 0.f, s1 = 0.f, s2 = 0.f, s3 = 0.f;
        while (q + 3 * T < total_q) {
            float c0 = __ldg(pred + fidx);
            float c1 = __ldg(pred + fidx + finc);
            float c2 = __ldg(pred + fidx + 2 * finc);
            float c3 = __ldg(pred + fidx + 3 * finc);
            s0 = fmaf(c0, c0, s0);
            s1 = fmaf(c1, c1, s1);
            s2 = fmaf(c2, c2, s2);
            s3 = fmaf(c3, c3, s3);
            q += 4 * T;
            fidx += 4 * finc;
        }
        while (q < total_q) {
            float c = __ldg(pred + fidx);
            s0 = fmaf(c, c, s0);
            q += T;
            fidx += finc;
        }
        facc += 0.5f * ((s0 + s1) + (s2 + s3));
    }

    // ============ reduce ======================================================
    #pragma unroll
    for (int o = 16; o; o >>= 1)
        facc += __shfl_xor_sync(0xFFFFFFFFu, facc, o);
    if (lane == 0) atomicAdd(&bsum, (double)facc);
    __syncthreads();

    if (tid == 0) {
        atomicAdd(&g_acc, bsum);
        __threadfence();
        unsigned done = atomicAdd(&g_count, 1u);
        if (done == (unsigned)(NBLOCKS - 1)) {
            double total = atomicAdd(&g_acc, 0.0);   // coherent read of final sum
            out[0] = (float)total;
            g_acc = 0.0;          // reset for next graph replay
            g_count = 0u;
        }
    }
}

extern "C" void kernel_launch(void* const* d_in, const int* in_sizes, int n_in,
                              void* d_out, int out_size)
{
    const float* pred    = (const float*)d_in[0];   // [batch, 5880]
    const float* boxes   = (const float*)d_in[1];   // [batch, 16, 4]
    const int*   classes = (const int*)d_in[2];     // [batch, 16]
    float* out = (float*)d_out;

    int batch = in_sizes[0] / IMG_FLOATS;

    yolo_kernel<<<NBLOCKS, NTHREADS>>>(pred, boxes, classes, out, batch);
}